// round 1
// baseline (speedup 1.0000x reference)
#include <cuda_runtime.h>
#include <math.h>
#include <stddef.h>

#define NN   100000
#define EE   800000
#define CH   256
#define COUT 40
#define BN_EPS 1e-5f

// ---------------- scratch (device globals: no runtime allocation) ----------------
__device__ float g_t[(size_t)NN * CH];    // GEMM output
__device__ float g_agg[(size_t)NN * CH];  // aggregated (GCN output pre-BN)
__device__ float g_h[(size_t)NN * CH];    // post-BN/ReLU activations
__device__ float g_dis[NN];               // deg^{-1/2}
__device__ int   g_deg[NN];               // in-degree counts
__device__ float g_stats[2 * CH];         // [sum, sumsq] per channel
__device__ float g_mu[CH];
__device__ float g_inv[CH];
__device__ float g_pool[CH];
__device__ float g_vx[CH];
__device__ float g_rowvec[CH];

// ---------------- degree / normalization ----------------
__global__ void zero_deg_kernel(int* deg) {
    int i = blockIdx.x * blockDim.x + threadIdx.x;
    if (i < NN) deg[i] = 0;
}

__global__ void count_deg_kernel(const int* __restrict__ dst, int* __restrict__ deg) {
    int e = blockIdx.x * blockDim.x + threadIdx.x;
    if (e < EE) atomicAdd(&deg[dst[e]], 1);
}

__global__ void compute_dis_kernel(const int* __restrict__ deg, float* __restrict__ dis) {
    int i = blockIdx.x * blockDim.x + threadIdx.x;
    if (i < NN) dis[i] = rsqrtf((float)deg[i] + 1.0f);
}

// ---------------- tiled fp32 GEMM with row-vector epilogue ----------------
// C[m][n] = sum_k A[m][k]*B[k][n] + rowvec[n]
template <int BM, int BN, int BK, int TM, int TN>
__global__ void sgemm_rowvec_kernel(const float* __restrict__ A,
                                    const float* __restrict__ B,
                                    const float* __restrict__ rowvec,
                                    float* __restrict__ C,
                                    int M, int Ncols, int K) {
    constexpr int NT = (BM / TM) * (BN / TN);
    __shared__ float As[BK][BM];   // transposed A tile
    __shared__ float Bs[BK][BN];

    const int tid = threadIdx.x;
    const int m0 = blockIdx.y * BM;
    const int n0 = blockIdx.x * BN;
    const int tx = tid % (BN / TN);
    const int ty = tid / (BN / TN);

    float acc[TM][TN];
#pragma unroll
    for (int i = 0; i < TM; i++)
#pragma unroll
        for (int j = 0; j < TN; j++) acc[i][j] = 0.0f;

    for (int k0 = 0; k0 < K; k0 += BK) {
        // A tile: BM x BK, stored transposed
#pragma unroll
        for (int i = tid; i < BM * BK / 4; i += NT) {
            int r  = i / (BK / 4);
            int c4 = (i % (BK / 4)) * 4;
            float4 v = make_float4(0.f, 0.f, 0.f, 0.f);
            if (m0 + r < M)
                v = *reinterpret_cast<const float4*>(&A[(size_t)(m0 + r) * K + k0 + c4]);
            As[c4 + 0][r] = v.x;
            As[c4 + 1][r] = v.y;
            As[c4 + 2][r] = v.z;
            As[c4 + 3][r] = v.w;
        }
        // B tile: BK x BN
#pragma unroll
        for (int i = tid; i < BK * BN / 4; i += NT) {
            int kr = i / (BN / 4);
            int c4 = (i % (BN / 4)) * 4;
            int col = n0 + c4;
            float4 v = make_float4(0.f, 0.f, 0.f, 0.f);
            if (col + 4 <= Ncols)
                v = *reinterpret_cast<const float4*>(&B[(size_t)(k0 + kr) * Ncols + col]);
            *reinterpret_cast<float4*>(&Bs[kr][c4]) = v;
        }
        __syncthreads();

#pragma unroll
        for (int k = 0; k < BK; k++) {
            float ra[TM], rb[TN];
#pragma unroll
            for (int i = 0; i < TM; i += 4)
                *reinterpret_cast<float4*>(&ra[i]) =
                    *reinterpret_cast<const float4*>(&As[k][ty * TM + i]);
#pragma unroll
            for (int j = 0; j < TN; j += 4)
                *reinterpret_cast<float4*>(&rb[j]) =
                    *reinterpret_cast<const float4*>(&Bs[k][tx * TN + j]);
#pragma unroll
            for (int i = 0; i < TM; i++)
#pragma unroll
                for (int j = 0; j < TN; j++)
                    acc[i][j] = fmaf(ra[i], rb[j], acc[i][j]);
        }
        __syncthreads();
    }

#pragma unroll
    for (int i = 0; i < TM; i++) {
        int m = m0 + ty * TM + i;
        if (m >= M) continue;
#pragma unroll
        for (int j = 0; j < TN; j += 4) {
            int n = n0 + tx * TN + j;
            if (n + 4 <= Ncols) {
                float4 rv = *reinterpret_cast<const float4*>(&rowvec[n]);
                float4 o;
                o.x = acc[i][j + 0] + rv.x;
                o.y = acc[i][j + 1] + rv.y;
                o.z = acc[i][j + 2] + rv.z;
                o.w = acc[i][j + 3] + rv.w;
                *reinterpret_cast<float4*>(&C[(size_t)m * Ncols + n]) = o;
            }
        }
    }
}

// ---------------- GCN aggregation ----------------
// agg = t * self_coef(row) + bias(col)   (self-loop term + bias)
__global__ void init_agg_kernel(const float* __restrict__ t, const float* __restrict__ dis,
                                const float* __restrict__ bias, float* __restrict__ agg,
                                int total4, int C) {
    int idx = blockIdx.x * blockDim.x + threadIdx.x;
    if (idx >= total4) return;
    int c4div = C / 4;
    int row = idx / c4div;
    int c4  = (idx % c4div) * 4;
    float d = dis[row];
    float sc = d * d;
    float4 v = *reinterpret_cast<const float4*>(&t[(size_t)row * C + c4]);
    float4 b = *reinterpret_cast<const float4*>(&bias[c4]);
    float4 o;
    o.x = fmaf(v.x, sc, b.x);
    o.y = fmaf(v.y, sc, b.y);
    o.z = fmaf(v.z, sc, b.z);
    o.w = fmaf(v.w, sc, b.w);
    *reinterpret_cast<float4*>(&agg[(size_t)row * C + c4]) = o;
}

// agg[dst] += t[src] * (dis[src]*dis[dst]) — vector float4 reductions
__global__ void scatter_edges_kernel(const int* __restrict__ src, const int* __restrict__ dst,
                                     const float* __restrict__ dis, const float* __restrict__ t,
                                     float* __restrict__ agg, int C) {
    int idx = blockIdx.x * blockDim.x + threadIdx.x;
    int chunks = C / 4;
    int e = idx / chunks;
    if (e >= EE) return;
    int c4 = (idx % chunks) * 4;
    int s = src[e];
    int d = dst[e];
    float coef = dis[s] * dis[d];
    float4 v = *reinterpret_cast<const float4*>(&t[(size_t)s * C + c4]);
    float vx = v.x * coef, vy = v.y * coef, vz = v.z * coef, vw = v.w * coef;
    float* p = &agg[(size_t)d * C + c4];
    asm volatile("red.global.add.v4.f32 [%0], {%1, %2, %3, %4};"
                 :: "l"(p), "f"(vx), "f"(vy), "f"(vz), "f"(vw)
                 : "memory");
}

// ---------------- BatchNorm (batch stats) + ReLU + pool ----------------
__global__ void zero_small_kernel(float* stats, float* pool) {
    int c = threadIdx.x;
    stats[c] = 0.f;
    stats[c + CH] = 0.f;
    pool[c] = 0.f;
}

__global__ void stats_kernel(const float* __restrict__ h, float* __restrict__ stats) {
    int c = threadIdx.x;  // 256 threads = channels
    float s = 0.f, s2 = 0.f;
    for (int r = blockIdx.x; r < NN; r += gridDim.x) {
        float v = h[(size_t)r * CH + c];
        s += v;
        s2 += v * v;
    }
    atomicAdd(&stats[c], s);
    atomicAdd(&stats[CH + c], s2);
}

__global__ void finalize_stats_kernel(const float* __restrict__ stats,
                                      float* __restrict__ mu, float* __restrict__ inv) {
    int c = threadIdx.x;
    float m = stats[c] * (1.0f / (float)NN);
    float v = stats[CH + c] * (1.0f / (float)NN) - m * m;
    mu[c] = m;
    inv[c] = rsqrtf(v + BN_EPS);
}

__global__ void bn_apply_kernel(const float* __restrict__ agg,
                                const float* __restrict__ mu, const float* __restrict__ inv,
                                const float* __restrict__ g, const float* __restrict__ b,
                                float* __restrict__ h, float* __restrict__ pool) {
    int c = threadIdx.x;
    float a  = inv[c] * g[c];
    float bb = b[c] - mu[c] * a;
    float ps = 0.f;
    for (int r = blockIdx.x; r < NN; r += gridDim.x) {
        float v = fmaxf(fmaf(agg[(size_t)r * CH + c], a, bb), 0.f);
        h[(size_t)r * CH + c] = v;
        ps += v;
    }
    atomicAdd(&pool[c], ps);
}

// ---------------- virtual-node MLP ----------------
// rowvec[c] = sum_k vx[k] * W[k*cols + c]   (for the very first layer: vx = vn_emb)
__global__ void rowvec_from_vx_kernel(const float* __restrict__ vx, const float* __restrict__ W,
                                      float* __restrict__ rowvec, int cols) {
    __shared__ float s[CH];
    int c = threadIdx.x;
    s[c] = vx[c];
    __syncthreads();
    if (c < cols) {
        float acc = 0.f;
        for (int k = 0; k < CH; k++) acc = fmaf(s[k], W[(size_t)k * cols + c], acc);
        rowvec[c] = acc;
    }
}

// vx_new = relu(LN((pool + vx_prev) @ vnW + vnb));  rowvec = vx_new @ W_next
__global__ void vn_update_kernel(const float* __restrict__ pool, const float* __restrict__ vx_prev,
                                 const float* __restrict__ vnW, const float* __restrict__ vnb,
                                 const float* __restrict__ lng, const float* __restrict__ lnb,
                                 const float* __restrict__ Wnext, int next_cols,
                                 float* __restrict__ vx_out, float* __restrict__ rowvec) {
    __shared__ float s[CH];
    __shared__ float red[CH];
    __shared__ float vxs[CH];
    int c = threadIdx.x;
    s[c] = pool[c] + vx_prev[c];
    __syncthreads();
    float z = vnb[c];
    for (int k = 0; k < CH; k++) z = fmaf(s[k], vnW[(size_t)k * CH + c], z);
    red[c] = z;
    __syncthreads();
    for (int off = CH / 2; off; off >>= 1) {
        if (c < off) red[c] += red[c + off];
        __syncthreads();
    }
    float mu = red[0] * (1.0f / (float)CH);
    __syncthreads();
    float d = z - mu;
    red[c] = d * d;
    __syncthreads();
    for (int off = CH / 2; off; off >>= 1) {
        if (c < off) red[c] += red[c + off];
        __syncthreads();
    }
    float var = red[0] * (1.0f / (float)CH);
    float vx = fmaxf(fmaf(d * rsqrtf(var + BN_EPS), lng[c], lnb[c]), 0.f);
    vxs[c] = vx;
    vx_out[c] = vx;
    __syncthreads();
    if (c < next_cols) {
        float acc = 0.f;
        for (int k = 0; k < CH; k++) acc = fmaf(vxs[k], Wnext[(size_t)k * next_cols + c], acc);
        rowvec[c] = acc;
    }
}

// ---------------- log_softmax over 40 classes, one warp per row ----------------
__global__ void logsoftmax_kernel(const float* __restrict__ agg, float* __restrict__ out) {
    int warp = threadIdx.x >> 5;
    int lane = threadIdx.x & 31;
    int row = blockIdx.x * (blockDim.x >> 5) + warp;
    if (row >= NN) return;
    const float* a = agg + (size_t)row * COUT;
    float v0 = a[lane];                                   // lanes 0..31 -> cols 0..31
    float v1 = (lane < COUT - 32) ? a[32 + lane] : -1e30f;  // lanes 0..7 -> cols 32..39
    float m = fmaxf(v0, v1);
#pragma unroll
    for (int off = 16; off; off >>= 1) m = fmaxf(m, __shfl_xor_sync(0xffffffffu, m, off));
    float sum = expf(v0 - m) + ((lane < COUT - 32) ? expf(v1 - m) : 0.f);
#pragma unroll
    for (int off = 16; off; off >>= 1) sum += __shfl_xor_sync(0xffffffffu, sum, off);
    float l = m + logf(sum);
    out[(size_t)row * COUT + lane] = v0 - l;
    if (lane < COUT - 32) out[(size_t)row * COUT + 32 + lane] = v1 - l;
}

// ---------------- driver ----------------
extern "C" void kernel_launch(void* const* d_in, const int* in_sizes, int n_in,
                              void* d_out, int out_size) {
    const float* x      = (const float*)d_in[0];
    const int*   ei     = (const int*)d_in[1];
    const float* W0     = (const float*)d_in[2];
    const float* b0     = (const float*)d_in[3];
    const float* W1     = (const float*)d_in[4];
    const float* b1     = (const float*)d_in[5];
    const float* W2     = (const float*)d_in[6];
    const float* b2     = (const float*)d_in[7];
    const float* bn_g0  = (const float*)d_in[8];
    const float* bn_b0  = (const float*)d_in[9];
    const float* bn_g1  = (const float*)d_in[10];
    const float* bn_b1  = (const float*)d_in[11];
    const float* vn_emb = (const float*)d_in[12];
    const float* vn_W0  = (const float*)d_in[13];
    const float* vn_b0  = (const float*)d_in[14];
    const float* ln_g0  = (const float*)d_in[15];
    const float* ln_b0  = (const float*)d_in[16];
    const float* vn_W1  = (const float*)d_in[17];
    const float* vn_b1  = (const float*)d_in[18];
    const float* ln_g1  = (const float*)d_in[19];
    const float* ln_b1  = (const float*)d_in[20];
    float* out = (float*)d_out;

    const int* src = ei;
    const int* dst = ei + EE;

    float *t, *agg, *h, *dis, *stats, *mu, *inv, *pool, *vx, *rowvec;
    int* deg;
    cudaGetSymbolAddress((void**)&t, g_t);
    cudaGetSymbolAddress((void**)&agg, g_agg);
    cudaGetSymbolAddress((void**)&h, g_h);
    cudaGetSymbolAddress((void**)&dis, g_dis);
    cudaGetSymbolAddress((void**)&deg, g_deg);
    cudaGetSymbolAddress((void**)&stats, g_stats);
    cudaGetSymbolAddress((void**)&mu, g_mu);
    cudaGetSymbolAddress((void**)&inv, g_inv);
    cudaGetSymbolAddress((void**)&pool, g_pool);
    cudaGetSymbolAddress((void**)&vx, g_vx);
    cudaGetSymbolAddress((void**)&rowvec, g_rowvec);

    const int T = 256;
    const int STAT_BLOCKS = 2048;
    dim3 gemm_grid_wide(CH / 128, (NN + 127) / 128);
    dim3 gemm_grid_narrow(1, (NN + 127) / 128);
    int total4_wide  = NN * (CH / 4);
    int total4_narrow = NN * (COUT / 4);
    int scat_wide_blocks   = (int)(((long long)EE * (CH / 4) + T - 1) / T);
    int scat_narrow_blocks = (int)(((long long)EE * (COUT / 4) + T - 1) / T);

    // degree / normalization coefficients
    zero_deg_kernel<<<(NN + T - 1) / T, T>>>(deg);
    count_deg_kernel<<<(EE + T - 1) / T, T>>>(dst, deg);
    compute_dis_kernel<<<(NN + T - 1) / T, T>>>(deg, dis);

    // ---- layer 0 ----
    rowvec_from_vx_kernel<<<1, T>>>(vn_emb, W0, rowvec, CH);
    sgemm_rowvec_kernel<128, 128, 16, 8, 8><<<gemm_grid_wide, T>>>(x, W0, rowvec, t, NN, CH, CH);
    init_agg_kernel<<<(total4_wide + T - 1) / T, T>>>(t, dis, b0, agg, total4_wide, CH);
    scatter_edges_kernel<<<scat_wide_blocks, T>>>(src, dst, dis, t, agg, CH);
    zero_small_kernel<<<1, T>>>(stats, pool);
    stats_kernel<<<STAT_BLOCKS, T>>>(agg, stats);
    finalize_stats_kernel<<<1, T>>>(stats, mu, inv);
    bn_apply_kernel<<<STAT_BLOCKS, T>>>(agg, mu, inv, bn_g0, bn_b0, h, pool);
    vn_update_kernel<<<1, T>>>(pool, vn_emb, vn_W0, vn_b0, ln_g0, ln_b0, W1, CH, vx, rowvec);

    // ---- layer 1 ----
    sgemm_rowvec_kernel<128, 128, 16, 8, 8><<<gemm_grid_wide, T>>>(h, W1, rowvec, t, NN, CH, CH);
    init_agg_kernel<<<(total4_wide + T - 1) / T, T>>>(t, dis, b1, agg, total4_wide, CH);
    scatter_edges_kernel<<<scat_wide_blocks, T>>>(src, dst, dis, t, agg, CH);
    zero_small_kernel<<<1, T>>>(stats, pool);
    stats_kernel<<<STAT_BLOCKS, T>>>(agg, stats);
    finalize_stats_kernel<<<1, T>>>(stats, mu, inv);
    bn_apply_kernel<<<STAT_BLOCKS, T>>>(agg, mu, inv, bn_g1, bn_b1, h, pool);
    vn_update_kernel<<<1, T>>>(pool, vx, vn_W1, vn_b1, ln_g1, ln_b1, W2, COUT, vx, rowvec);

    // ---- layer 2 (output, 40 channels) ----
    sgemm_rowvec_kernel<128, 64, 16, 8, 4><<<gemm_grid_narrow, T>>>(h, W2, rowvec, t, NN, COUT, CH);
    init_agg_kernel<<<(total4_narrow + T - 1) / T, T>>>(t, dis, b2, agg, total4_narrow, COUT);
    scatter_edges_kernel<<<scat_narrow_blocks, T>>>(src, dst, dis, t, agg, COUT);
    logsoftmax_kernel<<<(NN + 7) / 8, T>>>(agg, out);
}

// round 3
// speedup vs baseline: 1.5480x; 1.5480x over previous
#include <cuda_runtime.h>
#include <math.h>
#include <stddef.h>
#include <stdint.h>

#define NN   100000
#define EE   800000
#define CH   256
#define COUT 40
#define BN_EPS 1e-5f

// ---------------- scratch (device globals) ----------------
__device__ float g_t[(size_t)NN * CH];     // GEMM output (pre-aggregation)
__device__ float g_aggA[(size_t)NN * CH];  // aggregated buffer A
__device__ float g_aggB[(size_t)NN * CH];  // aggregated buffer B
__device__ float g_dis[NN];
__device__ int   g_deg[NN];
__device__ float g_stats[2 * CH];
__device__ float g_bn_a[CH];
__device__ float g_bn_b[CH];
__device__ float g_pool[CH];
__device__ float g_vx[CH];
__device__ float g_rowvec[CH];
__device__ float g_s[CH];
__device__ float g_z[CH];

// ---------------- helpers ----------------
__device__ __forceinline__ uint32_t f2tf32(float x) {
    uint32_t u;
    asm("cvt.rna.tf32.f32 %0, %1;" : "=r"(u) : "f"(x));
    return u;
}

__device__ __forceinline__ void mma_tf32(float& c0, float& c1, float& c2, float& c3,
                                         uint32_t a0, uint32_t a1, uint32_t a2, uint32_t a3,
                                         uint32_t b0, uint32_t b1) {
    asm volatile("mma.sync.aligned.m16n8k8.row.col.f32.tf32.tf32.f32 "
                 "{%0,%1,%2,%3}, {%4,%5,%6,%7}, {%8,%9}, {%0,%1,%2,%3};"
                 : "+f"(c0), "+f"(c1), "+f"(c2), "+f"(c3)
                 : "r"(a0), "r"(a1), "r"(a2), "r"(a3), "r"(b0), "r"(b1));
}

// ---------------- degree / normalization ----------------
__global__ void zero_deg_kernel(int* deg) {
    int i = blockIdx.x * blockDim.x + threadIdx.x;
    if (i < NN) deg[i] = 0;
}
__global__ void count_deg_kernel(const int* __restrict__ dst, int* __restrict__ deg) {
    int e = blockIdx.x * blockDim.x + threadIdx.x;
    if (e < EE) atomicAdd(&deg[dst[e]], 1);
}
__global__ void compute_dis_kernel(const int* __restrict__ deg, float* __restrict__ dis) {
    int i = blockIdx.x * blockDim.x + threadIdx.x;
    if (i < NN) dis[i] = rsqrtf((float)deg[i] + 1.0f);
}

// ---------------- tf32 tensor-core GEMM ----------------
// C = op(A) @ B;  op(A) optionally applies BN+ReLU per column (channel) of A.
// Epilogue: t = C + rowvec;  agg = t * dis[m]^2 + bias
template <int BN_T, bool APPLY_BN>
__global__ void __launch_bounds__(256, 2)
mma_gemm_kernel(const float* __restrict__ A, const float* __restrict__ B,
                const float* __restrict__ rowvec, const float* __restrict__ bias,
                const float* __restrict__ dis,
                const float* __restrict__ bn_a, const float* __restrict__ bn_b,
                float* __restrict__ Tout, float* __restrict__ agg,
                int M, int Ncols, int K) {
    constexpr int BM = 128, BK = 32;
    constexpr int AS_STRIDE = BK + 4;    // 36 words -> conflict-free A frags
    constexpr int BS_STRIDE = BN_T + 8;  // stride%32==8 -> conflict-free B frags
    __shared__ uint32_t As[BM * AS_STRIDE];
    __shared__ uint32_t Bs[BK * BS_STRIDE];

    const int tid = threadIdx.x;
    const int wid = tid >> 5, lane = tid & 31;
    const int gid = lane >> 2, tig = lane & 3;
    const int wm = wid & 3, wn = wid >> 2;           // 4x2 warp grid
    constexpr int WM = 32, WN = BN_T / 2;
    constexpr int MT = WM / 16;                      // 2
    constexpr int NT = WN / 8;                       // 8 (wide) / 4 (narrow)
    const int m0 = blockIdx.y * BM, n0 = blockIdx.x * BN_T;

    float acc[MT][NT][4];
#pragma unroll
    for (int i = 0; i < MT; i++)
#pragma unroll
        for (int j = 0; j < NT; j++)
#pragma unroll
            for (int q = 0; q < 4; q++) acc[i][j][q] = 0.0f;

    for (int k0 = 0; k0 < K; k0 += BK) {
        // ---- A tile: BM x BK, row-major in SMEM ----
#pragma unroll
        for (int j = 0; j < (BM * BK) / (256 * 4); j++) {
            int idx = tid + j * 256;
            int r = idx >> 3, c4 = (idx & 7) * 4;
            int row = m0 + r;
            float4 v = make_float4(0.f, 0.f, 0.f, 0.f);
            if (row < M)
                v = *reinterpret_cast<const float4*>(&A[(size_t)row * K + k0 + c4]);
            if (APPLY_BN) {
                v.x = fmaxf(fmaf(v.x, bn_a[k0 + c4 + 0], bn_b[k0 + c4 + 0]), 0.f);
                v.y = fmaxf(fmaf(v.y, bn_a[k0 + c4 + 1], bn_b[k0 + c4 + 1]), 0.f);
                v.z = fmaxf(fmaf(v.z, bn_a[k0 + c4 + 2], bn_b[k0 + c4 + 2]), 0.f);
                v.w = fmaxf(fmaf(v.w, bn_a[k0 + c4 + 3], bn_b[k0 + c4 + 3]), 0.f);
            }
            uint4 u = make_uint4(f2tf32(v.x), f2tf32(v.y), f2tf32(v.z), f2tf32(v.w));
            *reinterpret_cast<uint4*>(&As[r * AS_STRIDE + c4]) = u;
        }
        // ---- B tile: BK x BN_T ----
#pragma unroll
        for (int j = 0; j < (BK * BN_T) / (256 * 4); j++) {
            int idx = tid + j * 256;
            int kr = idx / (BN_T / 4), c4 = (idx % (BN_T / 4)) * 4;
            int col = n0 + c4;
            float4 v = make_float4(0.f, 0.f, 0.f, 0.f);
            if (col + 4 <= Ncols)
                v = *reinterpret_cast<const float4*>(&B[(size_t)(k0 + kr) * Ncols + col]);
            uint4 u = make_uint4(f2tf32(v.x), f2tf32(v.y), f2tf32(v.z), f2tf32(v.w));
            *reinterpret_cast<uint4*>(&Bs[kr * BS_STRIDE + c4]) = u;
        }
        __syncthreads();

#pragma unroll
        for (int k8 = 0; k8 < BK; k8 += 8) {
            uint32_t bf[NT][2];
#pragma unroll
            for (int nt = 0; nt < NT; nt++) {
                int ncol = wn * WN + nt * 8 + gid;
                bf[nt][0] = Bs[(k8 + tig) * BS_STRIDE + ncol];
                bf[nt][1] = Bs[(k8 + tig + 4) * BS_STRIDE + ncol];
            }
#pragma unroll
            for (int mt = 0; mt < MT; mt++) {
                int mrow = wm * WM + mt * 16 + gid;
                uint32_t a0 = As[mrow * AS_STRIDE + k8 + tig];
                uint32_t a1 = As[(mrow + 8) * AS_STRIDE + k8 + tig];
                uint32_t a2 = As[mrow * AS_STRIDE + k8 + tig + 4];
                uint32_t a3 = As[(mrow + 8) * AS_STRIDE + k8 + tig + 4];
#pragma unroll
                for (int nt = 0; nt < NT; nt++)
                    mma_tf32(acc[mt][nt][0], acc[mt][nt][1], acc[mt][nt][2], acc[mt][nt][3],
                             a0, a1, a2, a3, bf[nt][0], bf[nt][1]);
            }
        }
        __syncthreads();
    }

    // ---- epilogue: t = acc + rowvec; agg = t*sc + bias ----
#pragma unroll
    for (int mt = 0; mt < MT; mt++) {
        int r0 = m0 + wm * WM + mt * 16 + gid;
        int r1 = r0 + 8;
        float d0 = (r0 < M) ? dis[r0] : 0.f;
        float d1 = (r1 < M) ? dis[r1] : 0.f;
        float sc0 = d0 * d0, sc1 = d1 * d1;
#pragma unroll
        for (int nt = 0; nt < NT; nt++) {
            int col = n0 + wn * WN + nt * 8 + tig * 2;
            if (col + 2 > Ncols) continue;
            float2 rv = *reinterpret_cast<const float2*>(&rowvec[col]);
            float2 bi = *reinterpret_cast<const float2*>(&bias[col]);
            if (r0 < M) {
                float t0 = acc[mt][nt][0] + rv.x;
                float t1 = acc[mt][nt][1] + rv.y;
                *reinterpret_cast<float2*>(&Tout[(size_t)r0 * Ncols + col]) = make_float2(t0, t1);
                *reinterpret_cast<float2*>(&agg[(size_t)r0 * Ncols + col]) =
                    make_float2(fmaf(t0, sc0, bi.x), fmaf(t1, sc0, bi.y));
            }
            if (r1 < M) {
                float t2 = acc[mt][nt][2] + rv.x;
                float t3 = acc[mt][nt][3] + rv.y;
                *reinterpret_cast<float2*>(&Tout[(size_t)r1 * Ncols + col]) = make_float2(t2, t3);
                *reinterpret_cast<float2*>(&agg[(size_t)r1 * Ncols + col]) =
                    make_float2(fmaf(t2, sc1, bi.x), fmaf(t3, sc1, bi.y));
            }
        }
    }
}

// ---------------- edge scatter: agg[dst] += t[src] * coef ----------------
__global__ void scatter_edges_kernel(const int* __restrict__ src, const int* __restrict__ dst,
                                     const float* __restrict__ dis, const float* __restrict__ t,
                                     float* __restrict__ agg, int C) {
    int idx = blockIdx.x * blockDim.x + threadIdx.x;
    int chunks = C / 4;
    int e = idx / chunks;
    if (e >= EE) return;
    int c4 = (idx % chunks) * 4;
    int s = src[e];
    int d = dst[e];
    float coef = dis[s] * dis[d];
    float4 v = *reinterpret_cast<const float4*>(&t[(size_t)s * C + c4]);
    float vx = v.x * coef, vy = v.y * coef, vz = v.z * coef, vw = v.w * coef;
    float* p = &agg[(size_t)d * C + c4];
    asm volatile("red.global.add.v4.f32 [%0], {%1, %2, %3, %4};"
                 :: "l"(p), "f"(vx), "f"(vy), "f"(vz), "f"(vw)
                 : "memory");
}

// ---------------- BN stats / pool ----------------
__global__ void zero_small_kernel(float* stats, float* pool, float* rowvec) {
    int c = threadIdx.x;
    stats[c] = 0.f;
    stats[c + CH] = 0.f;
    pool[c] = 0.f;
    if (rowvec) rowvec[c] = 0.f;
}

__global__ void stats_kernel(const float* __restrict__ h, float* __restrict__ stats) {
    int c = threadIdx.x;
    float s = 0.f, s2 = 0.f;
    for (int r = blockIdx.x; r < NN; r += gridDim.x) {
        float v = h[(size_t)r * CH + c];
        s += v;
        s2 += v * v;
    }
    atomicAdd(&stats[c], s);
    atomicAdd(&stats[CH + c], s2);
}

__global__ void finalize_stats_kernel(const float* __restrict__ stats,
                                      const float* __restrict__ g, const float* __restrict__ bv,
                                      float* __restrict__ bn_a, float* __restrict__ bn_b) {
    int c = threadIdx.x;
    float m = stats[c] * (1.0f / (float)NN);
    float v = stats[CH + c] * (1.0f / (float)NN) - m * m;
    float a = rsqrtf(v + BN_EPS) * g[c];
    bn_a[c] = a;
    bn_b[c] = bv[c] - m * a;
}

__global__ void pool_kernel(const float* __restrict__ agg,
                            const float* __restrict__ bn_a, const float* __restrict__ bn_b,
                            float* __restrict__ pool) {
    int c = threadIdx.x;
    float a = bn_a[c], b = bn_b[c];
    float ps = 0.f;
    for (int r = blockIdx.x; r < NN; r += gridDim.x)
        ps += fmaxf(fmaf(agg[(size_t)r * CH + c], a, b), 0.f);
    atomicAdd(&pool[c], ps);
}

// ---------------- virtual-node MLP (parallelized) ----------------
__global__ void vn_prep_kernel(const float* __restrict__ pool, const float* __restrict__ vx_prev,
                               const float* __restrict__ vnb,
                               float* __restrict__ s, float* __restrict__ z) {
    int c = threadIdx.x;
    s[c] = pool[c] + vx_prev[c];
    z[c] = vnb[c];
}

// z[c] += sum over k-range of s[k]*W[k][c]   (grid = 8 k-splits)
__global__ void vn_matvec_kernel(const float* __restrict__ s, const float* __restrict__ W,
                                 float* __restrict__ z, int cols) {
    __shared__ float ss[32];
    int c = threadIdx.x;
    int kb = blockIdx.x * 32;
    if (c < 32) ss[c] = s[kb + c];
    __syncthreads();
    if (c < cols) {
        float acc = 0.f;
#pragma unroll
        for (int k = 0; k < 32; k++) acc = fmaf(ss[k], W[(size_t)(kb + k) * cols + c], acc);
        atomicAdd(&z[c], acc);
    }
}

__global__ void vn_ln_kernel(const float* __restrict__ z,
                             const float* __restrict__ lng, const float* __restrict__ lnb,
                             float* __restrict__ vx_out, float* __restrict__ rowvec) {
    __shared__ float red[CH];
    int c = threadIdx.x;
    float zv = z[c];
    red[c] = zv;
    __syncthreads();
    for (int off = CH / 2; off; off >>= 1) {
        if (c < off) red[c] += red[c + off];
        __syncthreads();
    }
    float mu = red[0] * (1.0f / (float)CH);
    __syncthreads();
    float d = zv - mu;
    red[c] = d * d;
    __syncthreads();
    for (int off = CH / 2; off; off >>= 1) {
        if (c < off) red[c] += red[c + off];
        __syncthreads();
    }
    float var = red[0] * (1.0f / (float)CH);
    vx_out[c] = fmaxf(fmaf(d * rsqrtf(var + BN_EPS), lng[c], lnb[c]), 0.f);
    rowvec[c] = 0.f;  // prepare accumulator for next rowvec_matvec
}

// rowvec[c] += sum over k-range of vx[k]*W[k][c]   (grid = 8 k-splits)
__global__ void rowvec_matvec_kernel(const float* __restrict__ vx, const float* __restrict__ W,
                                     float* __restrict__ rowvec, int cols) {
    __shared__ float ss[32];
    int c = threadIdx.x;
    int kb = blockIdx.x * 32;
    if (c < 32) ss[c] = vx[kb + c];
    __syncthreads();
    if (c < cols) {
        float acc = 0.f;
#pragma unroll
        for (int k = 0; k < 32; k++) acc = fmaf(ss[k], W[(size_t)(kb + k) * cols + c], acc);
        atomicAdd(&rowvec[c], acc);
    }
}

// ---------------- log_softmax (one warp per row) ----------------
__global__ void logsoftmax_kernel(const float* __restrict__ agg, float* __restrict__ out) {
    int warp = threadIdx.x >> 5;
    int lane = threadIdx.x & 31;
    int row = blockIdx.x * (blockDim.x >> 5) + warp;
    if (row >= NN) return;
    const float* a = agg + (size_t)row * COUT;
    float v0 = a[lane];
    float v1 = (lane < COUT - 32) ? a[32 + lane] : -1e30f;
    float m = fmaxf(v0, v1);
#pragma unroll
    for (int off = 16; off; off >>= 1) m = fmaxf(m, __shfl_xor_sync(0xffffffffu, m, off));
    float sum = expf(v0 - m) + ((lane < COUT - 32) ? expf(v1 - m) : 0.f);
#pragma unroll
    for (int off = 16; off; off >>= 1) sum += __shfl_xor_sync(0xffffffffu, sum, off);
    float l = m + logf(sum);
    out[(size_t)row * COUT + lane] = v0 - l;
    if (lane < COUT - 32) out[(size_t)row * COUT + 32 + lane] = v1 - l;
}

// ---------------- driver ----------------
extern "C" void kernel_launch(void* const* d_in, const int* in_sizes, int n_in,
                              void* d_out, int out_size) {
    const float* x      = (const float*)d_in[0];
    const int*   ei     = (const int*)d_in[1];
    const float* W0     = (const float*)d_in[2];
    const float* b0     = (const float*)d_in[3];
    const float* W1     = (const float*)d_in[4];
    const float* b1     = (const float*)d_in[5];
    const float* W2     = (const float*)d_in[6];
    const float* b2     = (const float*)d_in[7];
    const float* bn_g0  = (const float*)d_in[8];
    const float* bn_b0  = (const float*)d_in[9];
    const float* bn_g1  = (const float*)d_in[10];
    const float* bn_b1  = (const float*)d_in[11];
    const float* vn_emb = (const float*)d_in[12];
    const float* vn_W0  = (const float*)d_in[13];
    const float* vn_b0  = (const float*)d_in[14];
    const float* ln_g0  = (const float*)d_in[15];
    const float* ln_b0  = (const float*)d_in[16];
    const float* vn_W1  = (const float*)d_in[17];
    const float* vn_b1  = (const float*)d_in[18];
    const float* ln_g1  = (const float*)d_in[19];
    const float* ln_b1  = (const float*)d_in[20];
    float* out = (float*)d_out;

    const int* src = ei;
    const int* dst = ei + EE;

    float *t, *aggA, *aggB, *dis, *stats, *bn_a, *bn_b, *pool, *vx, *rowvec, *s, *z;
    int* deg;
    cudaGetSymbolAddress((void**)&t, g_t);
    cudaGetSymbolAddress((void**)&aggA, g_aggA);
    cudaGetSymbolAddress((void**)&aggB, g_aggB);
    cudaGetSymbolAddress((void**)&dis, g_dis);
    cudaGetSymbolAddress((void**)&deg, g_deg);
    cudaGetSymbolAddress((void**)&stats, g_stats);
    cudaGetSymbolAddress((void**)&bn_a, g_bn_a);
    cudaGetSymbolAddress((void**)&bn_b, g_bn_b);
    cudaGetSymbolAddress((void**)&pool, g_pool);
    cudaGetSymbolAddress((void**)&vx, g_vx);
    cudaGetSymbolAddress((void**)&rowvec, g_rowvec);
    cudaGetSymbolAddress((void**)&s, g_s);
    cudaGetSymbolAddress((void**)&z, g_z);

    const int T = 256;
    const int STAT_BLOCKS = 1024;
    dim3 gemm_wide(CH / 128, (NN + 127) / 128);
    dim3 gemm_narrow(1, (NN + 127) / 128);
    int scat_wide_blocks   = (int)(((long long)EE * (CH / 4) + T - 1) / T);
    int scat_narrow_blocks = (int)(((long long)EE * (COUT / 4) + T - 1) / T);

    // degree / normalization
    zero_deg_kernel<<<(NN + T - 1) / T, T>>>(deg);
    count_deg_kernel<<<(EE + T - 1) / T, T>>>(dst, deg);
    compute_dis_kernel<<<(NN + T - 1) / T, T>>>(deg, dis);
    zero_small_kernel<<<1, T>>>(stats, pool, rowvec);

    // ---- layer 0 ----
    rowvec_matvec_kernel<<<8, T>>>(vn_emb, W0, rowvec, CH);
    mma_gemm_kernel<128, false><<<gemm_wide, T>>>(x, W0, rowvec, b0, dis,
                                                  nullptr, nullptr, t, aggA, NN, CH, CH);
    scatter_edges_kernel<<<scat_wide_blocks, T>>>(src, dst, dis, t, aggA, CH);
    stats_kernel<<<STAT_BLOCKS, T>>>(aggA, stats);
    finalize_stats_kernel<<<1, T>>>(stats, bn_g0, bn_b0, bn_a, bn_b);
    pool_kernel<<<STAT_BLOCKS, T>>>(aggA, bn_a, bn_b, pool);
    vn_prep_kernel<<<1, T>>>(pool, vn_emb, vn_b0, s, z);
    vn_matvec_kernel<<<8, T>>>(s, vn_W0, z, CH);
    vn_ln_kernel<<<1, T>>>(z, ln_g0, ln_b0, vx, rowvec);
    rowvec_matvec_kernel<<<8, T>>>(vx, W1, rowvec, CH);

    // ---- layer 1 ----
    mma_gemm_kernel<128, true><<<gemm_wide, T>>>(aggA, W1, rowvec, b1, dis,
                                                 bn_a, bn_b, t, aggB, NN, CH, CH);
    zero_small_kernel<<<1, T>>>(stats, pool, nullptr);
    scatter_edges_kernel<<<scat_wide_blocks, T>>>(src, dst, dis, t, aggB, CH);
    stats_kernel<<<STAT_BLOCKS, T>>>(aggB, stats);
    finalize_stats_kernel<<<1, T>>>(stats, bn_g1, bn_b1, bn_a, bn_b);
    pool_kernel<<<STAT_BLOCKS, T>>>(aggB, bn_a, bn_b, pool);
    vn_prep_kernel<<<1, T>>>(pool, vx, vn_b1, s, z);
    vn_matvec_kernel<<<8, T>>>(s, vn_W1, z, CH);
    vn_ln_kernel<<<1, T>>>(z, ln_g1, ln_b1, vx, rowvec);
    rowvec_matvec_kernel<<<8, T>>>(vx, W2, rowvec, COUT);

    // ---- layer 2 (output, 40 channels) ----
    mma_gemm_kernel<64, true><<<gemm_narrow, T>>>(aggB, W2, rowvec, b2, dis,
                                                  bn_a, bn_b, t, aggA, NN, COUT, CH);
    scatter_edges_kernel<<<scat_narrow_blocks, T>>>(src, dst, dis, t, aggA, COUT);
    logsoftmax_kernel<<<(NN + 7) / 8, T>>>(aggA, out);
}

// round 7
// speedup vs baseline: 1.9544x; 1.2626x over previous
#include <cuda_runtime.h>
#include <math.h>
#include <stddef.h>
#include <stdint.h>

#define NN   100000
#define EE   800000
#define CH   256
#define COUT 40
#define BN_EPS 1e-5f
#define SCAN_BLK 1024                     // elements per scan block
#define NSCAN ((NN + SCAN_BLK - 1) / SCAN_BLK)  // 98

// ---------------- scratch (device globals) ----------------
__device__ float g_t[(size_t)NN * CH];    // GEMM output
__device__ float g_agg[(size_t)NN * CH];  // aggregated (GCN output pre-BN)
__device__ float g_dis[NN];
__device__ int   g_deg[NN];
__device__ int   g_rowptr[NN + 1];
__device__ int   g_cursor[NN];
__device__ int   g_csr_src[EE];
__device__ int   g_partials[256];
__device__ float g_stats[2 * CH];
__device__ float g_bn_a[CH];
__device__ float g_bn_b[CH];
__device__ float g_pool[CH];
__device__ float g_vx[CH];
__device__ float g_rowvec[CH];
__device__ float g_s[CH];
__device__ float g_z[CH];

// ---------------- helpers ----------------
__device__ __forceinline__ uint32_t f2tf32(float x) {
    uint32_t u;
    asm("cvt.rna.tf32.f32 %0, %1;" : "=r"(u) : "f"(x));
    return u;
}

__device__ __forceinline__ void mma_tf32(float& c0, float& c1, float& c2, float& c3,
                                         uint32_t a0, uint32_t a1, uint32_t a2, uint32_t a3,
                                         uint32_t b0, uint32_t b1) {
    asm volatile("mma.sync.aligned.m16n8k8.row.col.f32.tf32.tf32.f32 "
                 "{%0,%1,%2,%3}, {%4,%5,%6,%7}, {%8,%9}, {%0,%1,%2,%3};"
                 : "+f"(c0), "+f"(c1), "+f"(c2), "+f"(c3)
                 : "r"(a0), "r"(a1), "r"(a2), "r"(a3), "r"(b0), "r"(b1));
}

// ---------------- degree / init ----------------
__global__ void zero_deg_kernel(int* __restrict__ deg, float* __restrict__ stats,
                                float* __restrict__ pool, float* __restrict__ rowvec) {
    int i = blockIdx.x * blockDim.x + threadIdx.x;
    if (i < NN) deg[i] = 0;
    if (i < CH) {
        stats[i] = 0.f;
        stats[i + CH] = 0.f;
        pool[i] = 0.f;
        rowvec[i] = 0.f;
    }
}
__global__ void count_deg_kernel(const int* __restrict__ dst, int* __restrict__ deg) {
    int e = blockIdx.x * blockDim.x + threadIdx.x;
    if (e < EE) atomicAdd(&deg[dst[e]], 1);
}
__global__ void compute_dis_kernel(const int* __restrict__ deg, float* __restrict__ dis) {
    int i = blockIdx.x * blockDim.x + threadIdx.x;
    if (i < NN) dis[i] = rsqrtf((float)deg[i] + 1.0f);
}

// ---------------- exclusive scan (3 phases) ----------------
__global__ void scan1_kernel(const int* __restrict__ deg, int* __restrict__ rp,
                             int* __restrict__ partials) {
    __shared__ int sm[256];
    int tid = threadIdx.x;
    int base = blockIdx.x * SCAN_BLK + tid * 4;
    int v[4];
    int s = 0;
#pragma unroll
    for (int i = 0; i < 4; i++) {
        v[i] = (base + i < NN) ? deg[base + i] : 0;
        s += v[i];
    }
    sm[tid] = s;
    __syncthreads();
#pragma unroll
    for (int off = 1; off < 256; off <<= 1) {
        int tv = (tid >= off) ? sm[tid - off] : 0;
        __syncthreads();
        sm[tid] += tv;
        __syncthreads();
    }
    int excl = sm[tid] - s;
    if (tid == 255) partials[blockIdx.x] = sm[255];
    int run = excl;
#pragma unroll
    for (int i = 0; i < 4; i++) {
        if (base + i < NN) rp[base + i] = run;
        run += v[i];
    }
}

__global__ void scan2_kernel(int* __restrict__ partials) {
    __shared__ int sm[128];
    int tid = threadIdx.x;  // 128 >= NSCAN
    int v = (tid < NSCAN) ? partials[tid] : 0;
    sm[tid] = v;
    __syncthreads();
#pragma unroll
    for (int off = 1; off < 128; off <<= 1) {
        int tv = (tid >= off) ? sm[tid - off] : 0;
        __syncthreads();
        sm[tid] += tv;
        __syncthreads();
    }
    if (tid < NSCAN) partials[tid] = sm[tid] - v;  // exclusive
}

__global__ void scan3_kernel(int* __restrict__ rp, const int* __restrict__ partials,
                             int* __restrict__ cursor) {
    int tid = threadIdx.x;
    int base = blockIdx.x * SCAN_BLK + tid * 4;
    int off = partials[blockIdx.x];
#pragma unroll
    for (int i = 0; i < 4; i++) {
        int idx = base + i;
        if (idx < NN) {
            int val = rp[idx] + off;
            rp[idx] = val;
            cursor[idx] = val;
        }
    }
    if (blockIdx.x == 0 && tid == 0) rp[NN] = EE;
}

__global__ void fill_csr_kernel(const int* __restrict__ src, const int* __restrict__ dst,
                                int* __restrict__ cursor, int* __restrict__ csr) {
    int e = blockIdx.x * blockDim.x + threadIdx.x;
    if (e >= EE) return;
    int slot = atomicAdd(&cursor[dst[e]], 1);
    csr[slot] = src[e];
}

// ---------------- tf32 tensor-core GEMM ----------------
// t = op(A) @ B + rowvec;  op(A) optionally BN+ReLU per column
template <int BN_T, bool APPLY_BN>
__global__ void __launch_bounds__(256, 2)
mma_gemm_kernel(const float* __restrict__ A, const float* __restrict__ B,
                const float* __restrict__ rowvec,
                const float* __restrict__ bn_a, const float* __restrict__ bn_b,
                float* __restrict__ Tout,
                int M, int Ncols, int K) {
    constexpr int BM = 128, BK = 32;
    constexpr int AS_STRIDE = BK + 4;
    constexpr int BS_STRIDE = BN_T + 8;
    __shared__ uint32_t As[BM * AS_STRIDE];
    __shared__ uint32_t Bs[BK * BS_STRIDE];

    const int tid = threadIdx.x;
    const int wid = tid >> 5, lane = tid & 31;
    const int gid = lane >> 2, tig = lane & 3;
    const int wm = wid & 3, wn = wid >> 2;
    constexpr int WM = 32, WN = BN_T / 2;
    constexpr int MT = WM / 16;
    constexpr int NT = WN / 8;
    const int m0 = blockIdx.y * BM, n0 = blockIdx.x * BN_T;

    float acc[MT][NT][4];
#pragma unroll
    for (int i = 0; i < MT; i++)
#pragma unroll
        for (int j = 0; j < NT; j++)
#pragma unroll
            for (int q = 0; q < 4; q++) acc[i][j][q] = 0.0f;

    for (int k0 = 0; k0 < K; k0 += BK) {
#pragma unroll
        for (int j = 0; j < (BM * BK) / (256 * 4); j++) {
            int idx = tid + j * 256;
            int r = idx >> 3, c4 = (idx & 7) * 4;
            int row = m0 + r;
            float4 v = make_float4(0.f, 0.f, 0.f, 0.f);
            if (row < M)
                v = *reinterpret_cast<const float4*>(&A[(size_t)row * K + k0 + c4]);
            if (APPLY_BN) {
                v.x = fmaxf(fmaf(v.x, bn_a[k0 + c4 + 0], bn_b[k0 + c4 + 0]), 0.f);
                v.y = fmaxf(fmaf(v.y, bn_a[k0 + c4 + 1], bn_b[k0 + c4 + 1]), 0.f);
                v.z = fmaxf(fmaf(v.z, bn_a[k0 + c4 + 2], bn_b[k0 + c4 + 2]), 0.f);
                v.w = fmaxf(fmaf(v.w, bn_a[k0 + c4 + 3], bn_b[k0 + c4 + 3]), 0.f);
            }
            uint4 u = make_uint4(f2tf32(v.x), f2tf32(v.y), f2tf32(v.z), f2tf32(v.w));
            *reinterpret_cast<uint4*>(&As[r * AS_STRIDE + c4]) = u;
        }
#pragma unroll
        for (int j = 0; j < (BK * BN_T) / (256 * 4); j++) {
            int idx = tid + j * 256;
            int kr = idx / (BN_T / 4), c4 = (idx % (BN_T / 4)) * 4;
            int col = n0 + c4;
            float4 v = make_float4(0.f, 0.f, 0.f, 0.f);
            if (col + 4 <= Ncols)
                v = *reinterpret_cast<const float4*>(&B[(size_t)(k0 + kr) * Ncols + col]);
            uint4 u = make_uint4(f2tf32(v.x), f2tf32(v.y), f2tf32(v.z), f2tf32(v.w));
            *reinterpret_cast<uint4*>(&Bs[kr * BS_STRIDE + c4]) = u;
        }
        __syncthreads();

#pragma unroll
        for (int k8 = 0; k8 < BK; k8 += 8) {
            uint32_t bf[NT][2];
#pragma unroll
            for (int nt = 0; nt < NT; nt++) {
                int ncol = wn * WN + nt * 8 + gid;
                bf[nt][0] = Bs[(k8 + tig) * BS_STRIDE + ncol];
                bf[nt][1] = Bs[(k8 + tig + 4) * BS_STRIDE + ncol];
            }
#pragma unroll
            for (int mt = 0; mt < MT; mt++) {
                int mrow = wm * WM + mt * 16 + gid;
                uint32_t a0 = As[mrow * AS_STRIDE + k8 + tig];
                uint32_t a1 = As[(mrow + 8) * AS_STRIDE + k8 + tig];
                uint32_t a2 = As[mrow * AS_STRIDE + k8 + tig + 4];
                uint32_t a3 = As[(mrow + 8) * AS_STRIDE + k8 + tig + 4];
#pragma unroll
                for (int nt = 0; nt < NT; nt++)
                    mma_tf32(acc[mt][nt][0], acc[mt][nt][1], acc[mt][nt][2], acc[mt][nt][3],
                             a0, a1, a2, a3, bf[nt][0], bf[nt][1]);
            }
        }
        __syncthreads();
    }

#pragma unroll
    for (int mt = 0; mt < MT; mt++) {
        int r0 = m0 + wm * WM + mt * 16 + gid;
        int r1 = r0 + 8;
#pragma unroll
        for (int nt = 0; nt < NT; nt++) {
            int col = n0 + wn * WN + nt * 8 + tig * 2;
            if (col + 2 > Ncols) continue;
            float2 rv = *reinterpret_cast<const float2*>(&rowvec[col]);
            if (r0 < M)
                *reinterpret_cast<float2*>(&Tout[(size_t)r0 * Ncols + col]) =
                    make_float2(acc[mt][nt][0] + rv.x, acc[mt][nt][1] + rv.y);
            if (r1 < M)
                *reinterpret_cast<float2*>(&Tout[(size_t)r1 * Ncols + col]) =
                    make_float2(acc[mt][nt][2] + rv.x, acc[mt][nt][3] + rv.y);
        }
    }
}

// ---------------- CSR gather aggregation (wide, C=256) + fused BN stats ----------------
#define GATHER_G 16
__global__ void __launch_bounds__(256)
gather_wide_kernel(const int* __restrict__ rp, const int* __restrict__ csr,
                   const float* __restrict__ dis, const float* __restrict__ t,
                   const float* __restrict__ bias,
                   float* __restrict__ agg, float* __restrict__ stats) {
    int c = threadIdx.x;
    float b = bias[c];
    float s1 = 0.f, s2 = 0.f;
    int n0 = blockIdx.x * GATHER_G;
#pragma unroll 1
    for (int g = 0; g < GATHER_G; g++) {
        int n = n0 + g;
        if (n >= NN) break;
        float dn = dis[n];
        float acc = fmaf(t[(size_t)n * CH + c], dn * dn, b);
        int e = rp[n], e1 = rp[n + 1];
        for (; e + 2 <= e1; e += 2) {
            int sa = csr[e];
            int sb = csr[e + 1];
            float ca = dis[sa] * dn;
            float cb = dis[sb] * dn;
            float va = t[(size_t)sa * CH + c];
            float vb = t[(size_t)sb * CH + c];
            acc = fmaf(va, ca, acc);
            acc = fmaf(vb, cb, acc);
        }
        if (e < e1) {
            int sa = csr[e];
            acc = fmaf(t[(size_t)sa * CH + c], dis[sa] * dn, acc);
        }
        agg[(size_t)n * CH + c] = acc;
        s1 += acc;
        s2 += acc * acc;
    }
    atomicAdd(&stats[c], s1);
    atomicAdd(&stats[CH + c], s2);
}

// ---------------- BN finalize / pool ----------------
__global__ void finalize_stats_kernel(const float* __restrict__ stats,
                                      const float* __restrict__ g, const float* __restrict__ bv,
                                      float* __restrict__ bn_a, float* __restrict__ bn_b) {
    int c = threadIdx.x;
    float m = stats[c] * (1.0f / (float)NN);
    float v = stats[CH + c] * (1.0f / (float)NN) - m * m;
    float a = rsqrtf(v + BN_EPS) * g[c];
    bn_a[c] = a;
    bn_b[c] = bv[c] - m * a;
}

__global__ void pool_kernel(const float* __restrict__ agg,
                            const float* __restrict__ bn_a, const float* __restrict__ bn_b,
                            float* __restrict__ pool) {
    int c = threadIdx.x;
    float a = bn_a[c], b = bn_b[c];
    float ps = 0.f;
    for (int r = blockIdx.x; r < NN; r += gridDim.x)
        ps += fmaxf(fmaf(agg[(size_t)r * CH + c], a, b), 0.f);
    atomicAdd(&pool[c], ps);
}

// ---------------- virtual-node MLP ----------------
__global__ void vn_prep_kernel(const float* __restrict__ pool, const float* __restrict__ vx_prev,
                               const float* __restrict__ vnb,
                               float* __restrict__ s, float* __restrict__ z) {
    int c = threadIdx.x;
    s[c] = pool[c] + vx_prev[c];
    z[c] = vnb[c];
}

__global__ void vn_matvec_kernel(const float* __restrict__ s, const float* __restrict__ W,
                                 float* __restrict__ z, int cols) {
    __shared__ float ss[32];
    int c = threadIdx.x;
    int kb = blockIdx.x * 32;
    if (c < 32) ss[c] = s[kb + c];
    __syncthreads();
    if (c < cols) {
        float acc = 0.f;
#pragma unroll
        for (int k = 0; k < 32; k++) acc = fmaf(ss[k], W[(size_t)(kb + k) * cols + c], acc);
        atomicAdd(&z[c], acc);
    }
}

// LayerNorm+ReLU; also re-zeros stats/pool/rowvec for the next layer
__global__ void vn_ln_kernel(const float* __restrict__ z,
                             const float* __restrict__ lng, const float* __restrict__ lnb,
                             float* __restrict__ vx_out, float* __restrict__ rowvec,
                             float* __restrict__ stats, float* __restrict__ pool) {
    __shared__ float red[CH];
    int c = threadIdx.x;
    float zv = z[c];
    red[c] = zv;
    __syncthreads();
    for (int off = CH / 2; off; off >>= 1) {
        if (c < off) red[c] += red[c + off];
        __syncthreads();
    }
    float mu = red[0] * (1.0f / (float)CH);
    __syncthreads();
    float d = zv - mu;
    red[c] = d * d;
    __syncthreads();
    for (int off = CH / 2; off; off >>= 1) {
        if (c < off) red[c] += red[c + off];
        __syncthreads();
    }
    float var = red[0] * (1.0f / (float)CH);
    vx_out[c] = fmaxf(fmaf(d * rsqrtf(var + BN_EPS), lng[c], lnb[c]), 0.f);
    rowvec[c] = 0.f;
    stats[c] = 0.f;
    stats[CH + c] = 0.f;
    pool[c] = 0.f;
}

__global__ void rowvec_matvec_kernel(const float* __restrict__ vx, const float* __restrict__ W,
                                     float* __restrict__ rowvec, int cols) {
    __shared__ float ss[32];
    int c = threadIdx.x;
    int kb = blockIdx.x * 32;
    if (c < 32) ss[c] = vx[kb + c];
    __syncthreads();
    if (c < cols) {
        float acc = 0.f;
#pragma unroll
        for (int k = 0; k < 32; k++) acc = fmaf(ss[k], W[(size_t)(kb + k) * cols + c], acc);
        atomicAdd(&rowvec[c], acc);
    }
}

// ---------------- final layer: CSR gather (C=40) + self + bias + log_softmax ----------------
__global__ void __launch_bounds__(256)
gather_out_kernel(const int* __restrict__ rp, const int* __restrict__ csr,
                  const float* __restrict__ dis, const float* __restrict__ t,
                  const float* __restrict__ bias, float* __restrict__ out) {
    int warp = threadIdx.x >> 5;
    int lane = threadIdx.x & 31;
    int n = blockIdx.x * 8 + warp;
    if (n >= NN) return;

    float dn = dis[n];
    const float* tn = t + (size_t)n * COUT;
    float acc0 = fmaf(tn[lane], dn * dn, bias[lane]);
    float acc1 = (lane < COUT - 32)
                     ? fmaf(tn[32 + lane], dn * dn, bias[32 + lane])
                     : -1e30f;

    int e = rp[n], e1 = rp[n + 1];
    for (; e + 2 <= e1; e += 2) {
        int sa = csr[e];
        int sb = csr[e + 1];
        float ca = dis[sa] * dn;
        float cb = dis[sb] * dn;
        const float* ta = t + (size_t)sa * COUT;
        const float* tb = t + (size_t)sb * COUT;
        float va0 = ta[lane];
        float vb0 = tb[lane];
        acc0 = fmaf(va0, ca, acc0);
        acc0 = fmaf(vb0, cb, acc0);
        if (lane < COUT - 32) {
            acc1 = fmaf(ta[32 + lane], ca, acc1);
            acc1 = fmaf(tb[32 + lane], cb, acc1);
        }
    }
    if (e < e1) {
        int sa = csr[e];
        float ca = dis[sa] * dn;
        const float* ta = t + (size_t)sa * COUT;
        acc0 = fmaf(ta[lane], ca, acc0);
        if (lane < COUT - 32) acc1 = fmaf(ta[32 + lane], ca, acc1);
    }

    float m = fmaxf(acc0, acc1);
#pragma unroll
    for (int off = 16; off; off >>= 1) m = fmaxf(m, __shfl_xor_sync(0xffffffffu, m, off));
    float sum = expf(acc0 - m) + ((lane < COUT - 32) ? expf(acc1 - m) : 0.f);
#pragma unroll
    for (int off = 16; off; off >>= 1) sum += __shfl_xor_sync(0xffffffffu, sum, off);
    float l = m + logf(sum);
    out[(size_t)n * COUT + lane] = acc0 - l;
    if (lane < COUT - 32) out[(size_t)n * COUT + 32 + lane] = acc1 - l;
}

// ---------------- driver ----------------
extern "C" void kernel_launch(void* const* d_in, const int* in_sizes, int n_in,
                              void* d_out, int out_size) {
    const float* x      = (const float*)d_in[0];
    const int*   ei     = (const int*)d_in[1];
    const float* W0     = (const float*)d_in[2];
    const float* b0     = (const float*)d_in[3];
    const float* W1     = (const float*)d_in[4];
    const float* b1     = (const float*)d_in[5];
    const float* W2     = (const float*)d_in[6];
    const float* b2     = (const float*)d_in[7];
    const float* bn_g0  = (const float*)d_in[8];
    const float* bn_b0  = (const float*)d_in[9];
    const float* bn_g1  = (const float*)d_in[10];
    const float* bn_b1  = (const float*)d_in[11];
    const float* vn_emb = (const float*)d_in[12];
    const float* vn_W0  = (const float*)d_in[13];
    const float* vn_b0  = (const float*)d_in[14];
    const float* ln_g0  = (const float*)d_in[15];
    const float* ln_b0  = (const float*)d_in[16];
    const float* vn_W1  = (const float*)d_in[17];
    const float* vn_b1  = (const float*)d_in[18];
    const float* ln_g1  = (const float*)d_in[19];
    const float* ln_b1  = (const float*)d_in[20];
    float* out = (float*)d_out;

    const int* src = ei;
    const int* dst = ei + EE;

    float *t, *agg, *dis, *stats, *bn_a, *bn_b, *pool, *vx, *rowvec, *s, *z;
    int *deg, *rowptr, *cursor, *csr, *partials;
    cudaGetSymbolAddress((void**)&t, g_t);
    cudaGetSymbolAddress((void**)&agg, g_agg);
    cudaGetSymbolAddress((void**)&dis, g_dis);
    cudaGetSymbolAddress((void**)&deg, g_deg);
    cudaGetSymbolAddress((void**)&rowptr, g_rowptr);
    cudaGetSymbolAddress((void**)&cursor, g_cursor);
    cudaGetSymbolAddress((void**)&csr, g_csr_src);
    cudaGetSymbolAddress((void**)&partials, g_partials);
    cudaGetSymbolAddress((void**)&stats, g_stats);
    cudaGetSymbolAddress((void**)&bn_a, g_bn_a);
    cudaGetSymbolAddress((void**)&bn_b, g_bn_b);
    cudaGetSymbolAddress((void**)&pool, g_pool);
    cudaGetSymbolAddress((void**)&vx, g_vx);
    cudaGetSymbolAddress((void**)&rowvec, g_rowvec);
    cudaGetSymbolAddress((void**)&s, g_s);
    cudaGetSymbolAddress((void**)&z, g_z);

    const int T = 256;
    const int STAT_BLOCKS = 1024;
    dim3 gemm_wide(CH / 128, (NN + 127) / 128);
    dim3 gemm_narrow(1, (NN + 127) / 128);
    int gather_blocks = (NN + GATHER_G - 1) / GATHER_G;

    // ---- CSR build + normalization ----
    zero_deg_kernel<<<(NN + T - 1) / T, T>>>(deg, stats, pool, rowvec);
    count_deg_kernel<<<(EE + T - 1) / T, T>>>(dst, deg);
    compute_dis_kernel<<<(NN + T - 1) / T, T>>>(deg, dis);
    scan1_kernel<<<NSCAN, 256>>>(deg, rowptr, partials);
    scan2_kernel<<<1, 128>>>(partials);
    scan3_kernel<<<NSCAN, 256>>>(rowptr, partials, cursor);
    fill_csr_kernel<<<(EE + T - 1) / T, T>>>(src, dst, cursor, csr);

    // ---- layer 0 ----
    rowvec_matvec_kernel<<<8, T>>>(vn_emb, W0, rowvec, CH);
    mma_gemm_kernel<128, false><<<gemm_wide, T>>>(x, W0, rowvec, nullptr, nullptr, t, NN, CH, CH);
    gather_wide_kernel<<<gather_blocks, T>>>(rowptr, csr, dis, t, b0, agg, stats);
    finalize_stats_kernel<<<1, T>>>(stats, bn_g0, bn_b0, bn_a, bn_b);
    pool_kernel<<<STAT_BLOCKS, T>>>(agg, bn_a, bn_b, pool);
    vn_prep_kernel<<<1, T>>>(pool, vn_emb, vn_b0, s, z);
    vn_matvec_kernel<<<8, T>>>(s, vn_W0, z, CH);
    vn_ln_kernel<<<1, T>>>(z, ln_g0, ln_b0, vx, rowvec, stats, pool);
    rowvec_matvec_kernel<<<8, T>>>(vx, W1, rowvec, CH);

    // ---- layer 1 ----
    mma_gemm_kernel<128, true><<<gemm_wide, T>>>(agg, W1, rowvec, bn_a, bn_b, t, NN, CH, CH);
    gather_wide_kernel<<<gather_blocks, T>>>(rowptr, csr, dis, t, b1, agg, stats);
    finalize_stats_kernel<<<1, T>>>(stats, bn_g1, bn_b1, bn_a, bn_b);
    pool_kernel<<<STAT_BLOCKS, T>>>(agg, bn_a, bn_b, pool);
    vn_prep_kernel<<<1, T>>>(pool, vx, vn_b1, s, z);
    vn_matvec_kernel<<<8, T>>>(s, vn_W1, z, CH);
    vn_ln_kernel<<<1, T>>>(z, ln_g1, ln_b1, vx, rowvec, stats, pool);
    rowvec_matvec_kernel<<<8, T>>>(vx, W2, rowvec, COUT);

    // ---- layer 2 (output, fused gather + log_softmax) ----
    mma_gemm_kernel<64, true><<<gemm_narrow, T>>>(agg, W2, rowvec, bn_a, bn_b, t, NN, COUT, CH);
    gather_out_kernel<<<(NN + 7) / 8, T>>>(rowptr, csr, dis, t, b2, out);
}